// round 16
// baseline (speedup 1.0000x reference)
#include <cuda_runtime.h>
#include <cuda_bf16.h>
#include <cstdint>
#include <math.h>

// ---------------- problem constants ----------------
#define BATCH     32768
#define NSPARSE   26
#define NDENSE    13
#define VOCAB     10000
#define EDIM      64
#define NHEAD     2
#define DHEAD     32
#define NLAYER    3
#define H1DIM     256
#define H2DIM     128
#define DNNIN     1677
#define KPAD      1728            // 27*64 ; dnn cols: [emb 0..1663 | dense | pad]
#define XCOLS     39
#define ATTFLAT   (NSPARSE*EDIM)  // 1664
#define QKVR_C    256
#define MROWS     (BATCH*NSPARSE)
#define STACKW    (ATTFLAT + H2DIM)

// ---------------- scratch ----------------
__device__ __nv_bfloat16  g_attA[(size_t)BATCH * ATTFLAT];
__device__ __nv_bfloat16  g_attB[(size_t)BATCH * ATTFLAT];
__device__ __nv_bfloat16  g_dnn_bf[(size_t)BATCH * KPAD];
__device__ __nv_bfloat16  g_h1_bf[(size_t)BATCH * H1DIM];
__device__ float          g_h2[(size_t)BATCH * H2DIM];
__device__ __nv_bfloat16  g_wqkvr_bf[NLAYER * QKVR_C * EDIM];  // [l][n][k]
__device__ __nv_bfloat16  g_w1_bf[H1DIM * KPAD];
__device__ __nv_bfloat16  g_w2_bf[H2DIM * H1DIM];

// ---------------- mma.sync helpers ----------------
__device__ __forceinline__ uint32_t smem_u32(const void* p) {
    uint32_t a;
    asm("{ .reg .u64 t; cvta.to.shared.u64 t, %1; cvt.u32.u64 %0, t; }" : "=r"(a) : "l"(p));
    return a;
}
#define LDSM_X4(d, addr) \
    asm volatile("ldmatrix.sync.aligned.m8n8.x4.shared.b16 {%0,%1,%2,%3}, [%4];" \
        : "=r"((d)[0]), "=r"((d)[1]), "=r"((d)[2]), "=r"((d)[3]) : "r"(addr))
#define LDSM_X4_T(d, addr) \
    asm volatile("ldmatrix.sync.aligned.m8n8.x4.trans.shared.b16 {%0,%1,%2,%3}, [%4];" \
        : "=r"((d)[0]), "=r"((d)[1]), "=r"((d)[2]), "=r"((d)[3]) : "r"(addr))

__device__ __forceinline__ void mma_bf16(float* c, const uint32_t* a,
                                         uint32_t b0, uint32_t b1) {
    asm volatile(
        "mma.sync.aligned.m16n8k16.row.col.f32.bf16.bf16.f32 "
        "{%0,%1,%2,%3},{%4,%5,%6,%7},{%8,%9},{%0,%1,%2,%3};"
        : "+f"(c[0]), "+f"(c[1]), "+f"(c[2]), "+f"(c[3])
        : "r"(a[0]), "r"(a[1]), "r"(a[2]), "r"(a[3]), "r"(b0), "r"(b1));
}
__device__ __forceinline__ uint32_t packbf(float a, float b) {
    __nv_bfloat162 h = __floats2bfloat162_rn(a, b);
    return *(uint32_t*)&h;
}

// ---------------- weight prep ----------------
__global__ __launch_bounds__(256)
void prep_qkvr(const float* __restrict__ Wq, const float* __restrict__ Wk,
               const float* __restrict__ Wv, const float* __restrict__ Wr) {
    int idx = blockIdx.x * 256 + threadIdx.x;
    if (idx >= NLAYER * QKVR_C * EDIM) return;
    int l = idx >> 14, rem = idx & 16383;
    int n = rem >> 6, k = rem & 63;
    const float* Ws[4] = {Wq, Wk, Wv, Wr};
    g_wqkvr_bf[idx] = __float2bfloat16_rn(Ws[n >> 6][(l * EDIM + k) * EDIM + (n & 63)]);
}
#define PREP12_W2OFF (H1DIM * KPAD)
#define PREP12_TOTAL (PREP12_W2OFF + H2DIM * H1DIM)
__global__ __launch_bounds__(256)
void prep_w12(const float* __restrict__ W1, const float* __restrict__ W2) {
    int idx = blockIdx.x * 256 + threadIdx.x;
    if (idx >= PREP12_TOTAL) return;
    if (idx < PREP12_W2OFF) {
        int n = idx / KPAD, k = idx % KPAD;
        float v = 0.f;
        if (k < ATTFLAT)               v = W1[(long)(13 + k) * H1DIM + n];
        else if (k < ATTFLAT + NDENSE) v = W1[(long)(k - ATTFLAT) * H1DIM + n];
        g_w1_bf[idx] = __float2bfloat16_rn(v);
    } else {
        int j = idx - PREP12_W2OFF;
        int n = j / H1DIM, k = j % H1DIM;
        g_w2_bf[j] = __float2bfloat16_rn(W2[(long)k * H2DIM + n]);
    }
}

// ---------------- embedding gather (feeds DNN branch only) ----------------
__global__ __launch_bounds__(256)
void gather_emb(const int* __restrict__ sidx, const float* __restrict__ emb) {
    int t = threadIdx.x;
    int row = blockIdx.x * 64 + (t >> 2);
    int part = t & 3;
    int b = row / NSPARSE, f = row - b * NSPARSE;
    int vrow = sidx[(long)b * NSPARSE + f];
    const float* src = emb + ((long)f * VOCAB + vrow) * EDIM + part * 16;
    float4 a0 = *(const float4*)src;
    float4 a1 = *(const float4*)(src + 4);
    float4 a2 = *(const float4*)(src + 8);
    float4 a3 = *(const float4*)(src + 12);
    uint4 o0, o1;
    o0.x = packbf(a0.x, a0.y); o0.y = packbf(a0.z, a0.w);
    o0.z = packbf(a1.x, a1.y); o0.w = packbf(a1.z, a1.w);
    o1.x = packbf(a2.x, a2.y); o1.y = packbf(a2.z, a2.w);
    o1.z = packbf(a3.x, a3.y); o1.w = packbf(a3.z, a3.w);
    __nv_bfloat16* dst = g_dnn_bf + (long)b * KPAD + f * EDIM + part * 16;
    *(uint4*)dst       = o0;
    *(uint4*)(dst + 8) = o1;
}
__global__ __launch_bounds__(256)
void dense_pad(const float* __restrict__ X) {
    long idx = (long)blockIdx.x * 256 + threadIdx.x;
    int b = (int)(idx >> 6), cc = (int)(idx & 63);
    float v = (cc < NDENSE) ? X[(long)b * XCOLS + NSPARSE + cc] : 0.f;
    g_dnn_bf[(long)b * KPAD + ATTFLAT + cc] = __float2bfloat16_rn(v);
}

// ---------------- fused proj + attention layer (tensor-core attention) ----
// 256 threads, 4 samples/CTA. GATHER=true: A tile gathered directly from
// fp32 emb tables via sidx (layer 1); else A read from bf16 att buffer.
#define F_SPB   4
#define SQROWB  528
#define OFF_A   0
#define OFF_Q   (112 * 128)                    // 14336
#define F_SMEM  (OFF_Q + 112 * SQROWB)         // 73472

template<bool GATHER>
__global__ __launch_bounds__(256, 3)
void fused_layer(const __nv_bfloat16* __restrict__ Ain, long sstride,
                 const int* __restrict__ sidx, const float* __restrict__ embf,
                 const __nv_bfloat16* __restrict__ W,
                 __nv_bfloat16* __restrict__ Aout) {
    extern __shared__ __align__(1024) unsigned char sm[];
    const int tid = threadIdx.x, wid = tid >> 5, lane = tid & 31;
    const long b0 = (long)blockIdx.x * F_SPB;

    // A tile: 112 rows x 128 B (rows 104..111 zero), swizzled
#pragma unroll 4
    for (int u = tid; u < 896; u += 256) {
        int r = u >> 3, ck = u & 7;
        uint4 v = make_uint4(0u, 0u, 0u, 0u);
        if (r < 104) {
            int s = r / 26, f = r - s * 26;
            if (GATHER) {
                int vrow = sidx[(b0 + s) * NSPARSE + f];
                const float* src = embf + ((long)f * VOCAB + vrow) * EDIM + ck * 8;
                float4 x0 = *(const float4*)src;
                float4 x1 = *(const float4*)(src + 4);
                v.x = packbf(x0.x, x0.y); v.y = packbf(x0.z, x0.w);
                v.z = packbf(x1.x, x1.y); v.w = packbf(x1.z, x1.w);
            } else {
                v = *(const uint4*)((const unsigned char*)(Ain + (b0 + s) * sstride + f * EDIM) + ck * 16);
            }
        }
        *(uint4*)(sm + OFF_A + r * 128 + ((ck ^ (r & 7)) << 4)) = v;
    }

    // W fragments direct from gmem: wf[kk][nt][0..1] for this warp's 32 cols.
    uint32_t wf[4][4][2];
    {
        const __nv_bfloat16* Wl = W + (lane >> 2) * 64 + (lane & 3) * 2;
#pragma unroll
        for (int nt = 0; nt < 4; nt++) {
            const __nv_bfloat16* Wn = Wl + (wid * 32 + nt * 8) * 64;
#pragma unroll
            for (int kk = 0; kk < 4; kk++) {
                wf[kk][nt][0] = *(const uint32_t*)(Wn + kk * 16);
                wf[kk][nt][1] = *(const uint32_t*)(Wn + kk * 16 + 8);
            }
        }
    }
    __syncthreads();

    const uint32_t sA = smem_u32(sm + OFF_A);
    const int sel = lane >> 3, rr = lane & 7;
    const int g = lane >> 2, t4 = lane & 3;

    // 7 m-tiles of 16 rows
    for (int mt = 0; mt < 7; mt++) {
        float acc[4][4];
#pragma unroll
        for (int ni = 0; ni < 4; ni++)
#pragma unroll
            for (int q = 0; q < 4; q++) acc[ni][q] = 0.f;
#pragma unroll
        for (int kk = 0; kk < 4; kk++) {
            uint32_t a[4];
            int ra = mt * 16 + (sel & 1) * 8 + rr;
            LDSM_X4(a, sA + ra * 128 + ((uint32_t)((2 * kk + (sel >> 1)) ^ (ra & 7)) << 4));
#pragma unroll
            for (int nt = 0; nt < 4; nt++)
                mma_bf16(acc[nt], a, wf[kk][nt][0], wf[kk][nt][1]);
        }
#pragma unroll
        for (int ni = 0; ni < 4; ni++) {
            int col = wid * 32 + ni * 8 + 2 * t4;
            int r0 = mt * 16 + g;
            *(uint32_t*)(sm + OFF_Q + (long)r0 * SQROWB + col * 2) = packbf(acc[ni][0], acc[ni][1]);
            *(uint32_t*)(sm + OFF_Q + (long)(r0 + 8) * SQROWB + col * 2) = packbf(acc[ni][2], acc[ni][3]);
        }
    }
    __syncthreads();

    // ---------- attention on tensor cores: warp -> (s = w>>1, h = w&1) ----
    const int s = wid >> 1, h = wid & 1;
    const uint32_t sQ = smem_u32(sm + OFF_Q) + (uint32_t)(s * 26 * SQROWB);

    // scores S[32,32]
    float sc[2][4][4];
#pragma unroll
    for (int mt = 0; mt < 2; mt++)
#pragma unroll
        for (int nt = 0; nt < 4; nt++)
#pragma unroll
            for (int q = 0; q < 4; q++) sc[mt][nt][q] = 0.f;

#pragma unroll
    for (int ks = 0; ks < 2; ks++) {
        uint32_t qf[2][4];
#pragma unroll
        for (int mt = 0; mt < 2; mt++) {
            int r = mt * 16 + (sel & 1) * 8 + rr;
            LDSM_X4(qf[mt], sQ + (uint32_t)(r * SQROWB + h * 64 + ks * 32 + (sel >> 1) * 16));
        }
#pragma unroll
        for (int ntp = 0; ntp < 2; ntp++) {
            int jn = ntp * 16 + (sel >> 1) * 8 + rr;
            uint32_t kf[4];
            LDSM_X4(kf, sQ + (uint32_t)(jn * SQROWB + 128 + h * 64 + ks * 32 + (sel & 1) * 16));
#pragma unroll
            for (int mt = 0; mt < 2; mt++) {
                mma_bf16(sc[mt][ntp * 2],     qf[mt], kf[0], kf[1]);
                mma_bf16(sc[mt][ntp * 2 + 1], qf[mt], kf[2], kf[3]);
            }
        }
    }
    // mask cols >= 26
#pragma unroll
    for (int mt = 0; mt < 2; mt++)
#pragma unroll
        for (int q = 0; q < 4; q++) {
            int col = 24 + 2 * t4 + (q & 1);
            if (col >= 26) sc[mt][3][q] = -INFINITY;
        }
    // softmax per row; in-lane then quad shuffles
#pragma unroll
    for (int mt = 0; mt < 2; mt++) {
#pragma unroll
        for (int half = 0; half < 2; half++) {
            float m = -INFINITY;
#pragma unroll
            for (int nt = 0; nt < 4; nt++)
                m = fmaxf(m, fmaxf(sc[mt][nt][half * 2], sc[mt][nt][half * 2 + 1]));
            m = fmaxf(m, __shfl_xor_sync(0xffffffffu, m, 1));
            m = fmaxf(m, __shfl_xor_sync(0xffffffffu, m, 2));
            float ssum = 0.f;
#pragma unroll
            for (int nt = 0; nt < 4; nt++) {
                float e0 = __expf(sc[mt][nt][half * 2] - m);
                float e1 = __expf(sc[mt][nt][half * 2 + 1] - m);
                sc[mt][nt][half * 2] = e0; sc[mt][nt][half * 2 + 1] = e1;
                ssum += e0 + e1;
            }
            ssum += __shfl_xor_sync(0xffffffffu, ssum, 1);
            ssum += __shfl_xor_sync(0xffffffffu, ssum, 2);
            float inv = 1.f / ssum;
#pragma unroll
            for (int nt = 0; nt < 4; nt++) {
                sc[mt][nt][half * 2] *= inv;
                sc[mt][nt][half * 2 + 1] *= inv;
            }
        }
    }
    // P fragments -> PV
    float ov[2][4][4];
#pragma unroll
    for (int mt = 0; mt < 2; mt++)
#pragma unroll
        for (int nt = 0; nt < 4; nt++)
#pragma unroll
            for (int q = 0; q < 4; q++) ov[mt][nt][q] = 0.f;

#pragma unroll
    for (int ks = 0; ks < 2; ks++) {
        uint32_t vb[2][4];
#pragma unroll
        for (int ntp = 0; ntp < 2; ntp++) {
            int j = ks * 16 + (sel & 1) * 8 + rr;
            int ntile = ntp * 2 + (sel >> 1);
            LDSM_X4_T(vb[ntp], sQ + (uint32_t)(j * SQROWB + 256 + h * 64 + ntile * 16));
        }
#pragma unroll
        for (int mt = 0; mt < 2; mt++) {
            uint32_t pa[4];
            pa[0] = packbf(sc[mt][2 * ks][0], sc[mt][2 * ks][1]);
            pa[1] = packbf(sc[mt][2 * ks][2], sc[mt][2 * ks][3]);
            pa[2] = packbf(sc[mt][2 * ks + 1][0], sc[mt][2 * ks + 1][1]);
            pa[3] = packbf(sc[mt][2 * ks + 1][2], sc[mt][2 * ks + 1][3]);
#pragma unroll
            for (int ntp = 0; ntp < 2; ntp++) {
                mma_bf16(ov[mt][ntp * 2],     pa, vb[ntp][0], vb[ntp][1]);
                mma_bf16(ov[mt][ntp * 2 + 1], pa, vb[ntp][2], vb[ntp][3]);
            }
        }
    }
    // residual (cols 192 + h*32 -> bytes 384 + h*64) + relu + store
    __nv_bfloat16* outb = Aout + (b0 + s) * ATTFLAT + h * DHEAD;
#pragma unroll
    for (int mt = 0; mt < 2; mt++) {
#pragma unroll
        for (int nt = 0; nt < 4; nt++) {
            int col = nt * 8 + 2 * t4;
            int r0 = mt * 16 + g;
            {
                uint32_t ru = *(const uint32_t*)(sm + OFF_Q + (s * 26 + r0) * SQROWB + 384 + h * 64 + col * 2);
                float2 rf = __bfloat1622float2(*(__nv_bfloat162*)&ru);
                float o0 = fmaxf(ov[mt][nt][0] + rf.x, 0.f);
                float o1 = fmaxf(ov[mt][nt][1] + rf.y, 0.f);
                *(uint32_t*)(outb + (size_t)r0 * EDIM + col) = packbf(o0, o1);
            }
            int r1 = r0 + 8;
            if (mt == 0 || g < 2) {
                uint32_t ru = *(const uint32_t*)(sm + OFF_Q + (s * 26 + r1) * SQROWB + 384 + h * 64 + col * 2);
                float2 rf = __bfloat1622float2(*(__nv_bfloat162*)&ru);
                float o0 = fmaxf(ov[mt][nt][2] + rf.x, 0.f);
                float o1 = fmaxf(ov[mt][nt][3] + rf.y, 0.f);
                *(uint32_t*)(outb + (size_t)r1 * EDIM + col) = packbf(o0, o1);
            }
        }
    }
}

// ---------------- bf16 mma.sync GEMM (dnn layers) ----------------
template<int KTOT, int NTFULL, bool RELU, bool BF16OUT>
__global__ __launch_bounds__(256)
void gemm_mma(const __nv_bfloat16* __restrict__ A,
              const __nv_bfloat16* __restrict__ Bop,
              const float* __restrict__ bias,
              void* __restrict__ Cout) {
    __shared__ __align__(1024) unsigned char smA[128 * 128];
    __shared__ __align__(1024) unsigned char smB[128 * 128];
    const int tid = threadIdx.x;
    const int wid = tid >> 5, lane = tid & 31;
    const int wm = wid & 3, wn = wid >> 2;
    const long m0 = (long)blockIdx.x * 128;
    const int n0 = blockIdx.y * 128;

    float acc[2][8][4];
#pragma unroll
    for (int mi = 0; mi < 2; mi++)
#pragma unroll
        for (int ni = 0; ni < 8; ni++)
#pragma unroll
            for (int q = 0; q < 4; q++) acc[mi][ni][q] = 0.f;

    const uint32_t sA = smem_u32(smA), sB = smem_u32(smB);
    const int sel = lane >> 3, rr = lane & 7;
    const int arow0 = wm * 32 + (sel & 1) * 8 + rr;
    const int ahi = sel >> 1;
    const int brow0 = wn * 64 + (sel >> 1) * 8 + rr;
    const int bhi = sel & 1;

    const int NCH = KTOT / 64;
    for (int ch = 0; ch < NCH; ch++) {
        const unsigned char* Ag = (const unsigned char*)A + (m0 * KTOT + (long)ch * 64) * 2;
        const unsigned char* Bg = (const unsigned char*)Bop + (((long)n0 * KTOT) + (long)ch * 64) * 2;
#pragma unroll 2
        for (int u = tid; u < 1024; u += 256) {
            int r = u >> 3, ck = u & 7;
            uint32_t so = (uint32_t)(r * 128 + ((ck ^ (r & 7)) << 4));
            *(uint4*)(smA + so) = *(const uint4*)(Ag + (long)r * (KTOT * 2) + ck * 16);
            *(uint4*)(smB + so) = *(const uint4*)(Bg + (long)r * (KTOT * 2) + ck * 16);
        }
        __syncthreads();
#pragma unroll
        for (int kk = 0; kk < 4; kk++) {
            uint32_t a[2][4];
#pragma unroll
            for (int mi = 0; mi < 2; mi++) {
                int r = arow0 + mi * 16;
                LDSM_X4(a[mi], sA + r * 128 + ((uint32_t)((2 * kk + ahi) ^ (r & 7)) << 4));
            }
#pragma unroll
            for (int nip = 0; nip < 4; nip++) {
                int r = brow0 + nip * 16;
                uint32_t b[4];
                LDSM_X4(b, sB + r * 128 + ((uint32_t)((2 * kk + bhi) ^ (r & 7)) << 4));
#pragma unroll
                for (int mi = 0; mi < 2; mi++) {
                    mma_bf16(acc[mi][nip * 2],     a[mi], b[0], b[1]);
                    mma_bf16(acc[mi][nip * 2 + 1], a[mi], b[2], b[3]);
                }
            }
        }
        __syncthreads();
    }

    const int g = lane >> 2, t = lane & 3;
#pragma unroll
    for (int mi = 0; mi < 2; mi++) {
#pragma unroll
        for (int ni = 0; ni < 8; ni++) {
            int col = n0 + wn * 64 + ni * 8 + 2 * t;
            long r0 = m0 + wm * 32 + mi * 16 + g;
            float c0 = acc[mi][ni][0], c1 = acc[mi][ni][1];
            float c2 = acc[mi][ni][2], c3 = acc[mi][ni][3];
            if (bias != nullptr) {
                float bb0 = bias[col], bb1 = bias[col + 1];
                c0 += bb0; c1 += bb1; c2 += bb0; c3 += bb1;
            }
            if (RELU) {
                c0 = fmaxf(c0, 0.f); c1 = fmaxf(c1, 0.f);
                c2 = fmaxf(c2, 0.f); c3 = fmaxf(c3, 0.f);
            }
            if (BF16OUT) {
                __nv_bfloat16* base = (__nv_bfloat16*)Cout;
                *(uint32_t*)(base + r0 * NTFULL + col)       = packbf(c0, c1);
                *(uint32_t*)(base + (r0 + 8) * NTFULL + col) = packbf(c2, c3);
            } else {
                float* base = (float*)Cout;
                *(float2*)(base + r0 * NTFULL + col)       = make_float2(c0, c1);
                *(float2*)(base + (r0 + 8) * NTFULL + col) = make_float2(c2, c3);
            }
        }
    }
}

// ---------------- head ----------------
__global__ __launch_bounds__(256)
void head_kernel(const float* __restrict__ X,
                 const __nv_bfloat16* __restrict__ att,
                 const float* __restrict__ outW,
                 const float* __restrict__ linW, const float* __restrict__ linb,
                 float* __restrict__ out) {
    __shared__ __align__(16) float soW[STACKW];
    int tid = threadIdx.x;
    for (int i = tid; i < STACKW; i += 256) soW[i] = outW[i];
    __syncthreads();
    int warp = tid >> 5, lane = tid & 31;
    int s = blockIdx.x * 8 + warp;
    const uint4* ap = (const uint4*)(att + (size_t)s * ATTFLAT);
    float acc = 0.f;
#pragma unroll
    for (int t = 0; t < 7; t++) {
        int i = t * 32 + lane;
        if (t < 6 || lane < 16) {
            uint4 u = ap[i];
            const __nv_bfloat162* hb = (const __nv_bfloat162*)&u;
            const float* w = &soW[i * 8];
#pragma unroll
            for (int q = 0; q < 4; q++) {
                float2 f2 = __bfloat1622float2(hb[q]);
                acc += f2.x * w[2 * q] + f2.y * w[2 * q + 1];
            }
        }
    }
    {
        const float4* hp = (const float4*)&g_h2[(size_t)s * H2DIM];
        float4 a = hp[lane];
        const float4* ow4 = (const float4*)soW;
        float4 w = ow4[ATTFLAT / 4 + lane];
        acc += a.x * w.x + a.y * w.y + a.z * w.z + a.w * w.w;
    }
    float al = X[(size_t)s * XCOLS + lane] * linW[lane];
    if (lane < XCOLS - 32) al += X[(size_t)s * XCOLS + 32 + lane] * linW[32 + lane];
#pragma unroll
    for (int o = 16; o > 0; o >>= 1) {
        acc += __shfl_xor_sync(0xffffffffu, acc, o);
        al  += __shfl_xor_sync(0xffffffffu, al, o);
    }
    if (lane == 0) {
        float lin = fmaxf(al + linb[0], 0.f);
        out[s] = 1.f / (1.f + expf(-(lin + acc)));
    }
}

// ---------------- launcher ----------------
extern "C" void kernel_launch(void* const* d_in, const int* in_sizes, int n_in,
                              void* d_out, int out_size) {
    (void)in_sizes; (void)n_in; (void)out_size;
    const float* X    = (const float*)d_in[0];
    const int*   sidx = (const int*)  d_in[1];
    const float* emb  = (const float*)d_in[2];
    const float* Wq   = (const float*)d_in[3];
    const float* Wk   = (const float*)d_in[4];
    const float* Wv   = (const float*)d_in[5];
    const float* Wr   = (const float*)d_in[6];
    const float* W1   = (const float*)d_in[7];
    const float* b1   = (const float*)d_in[8];
    const float* W2   = (const float*)d_in[9];
    const float* b2   = (const float*)d_in[10];
    const float* outW = (const float*)d_in[11];
    const float* linW = (const float*)d_in[12];
    const float* linb = (const float*)d_in[13];
    float* out = (float*)d_out;

    void *pAttA, *pAttB, *pDnn, *pH1, *pH2, *pWqkvr, *pW1b, *pW2b;
    cudaGetSymbolAddress(&pAttA,  g_attA);
    cudaGetSymbolAddress(&pAttB,  g_attB);
    cudaGetSymbolAddress(&pDnn,   g_dnn_bf);
    cudaGetSymbolAddress(&pH1,    g_h1_bf);
    cudaGetSymbolAddress(&pH2,    g_h2);
    cudaGetSymbolAddress(&pWqkvr, g_wqkvr_bf);
    cudaGetSymbolAddress(&pW1b,   g_w1_bf);
    cudaGetSymbolAddress(&pW2b,   g_w2_bf);

    cudaFuncSetAttribute((const void*)fused_layer<true>,
                         cudaFuncAttributeMaxDynamicSharedMemorySize, F_SMEM);
    cudaFuncSetAttribute((const void*)fused_layer<false>,
                         cudaFuncAttributeMaxDynamicSharedMemorySize, F_SMEM);

    // side stream + fork/join events (created once; identical work every call)
    static cudaStream_t s2 = nullptr;
    static cudaEvent_t evFork = nullptr, evJoin = nullptr;
    if (s2 == nullptr) {
        cudaStreamCreateWithFlags(&s2, cudaStreamNonBlocking);
        cudaEventCreateWithFlags(&evFork, cudaEventDisableTiming);
        cudaEventCreateWithFlags(&evJoin, cudaEventDisableTiming);
    }

    // fork immediately: DNN branch on s2 (gather feeds only the DNN path now)
    cudaEventRecord(evFork, 0);
    cudaStreamWaitEvent(s2, evFork, 0);
    prep_w12<<<(PREP12_TOTAL + 255) / 256, 256, 0, s2>>>(W1, W2);
    gather_emb<<<MROWS / 64, 256, 0, s2>>>(sidx, emb);
    dense_pad<<<BATCH * 64 / 256, 256, 0, s2>>>(X);
    gemm_mma<KPAD, H1DIM, true, true><<<dim3(BATCH / 128, H1DIM / 128), 256, 0, s2>>>(
        (const __nv_bfloat16*)pDnn, (const __nv_bfloat16*)pW1b, b1, pH1);
    gemm_mma<H1DIM, H2DIM, true, false><<<dim3(BATCH / 128, 1), 256, 0, s2>>>(
        (const __nv_bfloat16*)pH1, (const __nv_bfloat16*)pW2b, b2, pH2);
    cudaEventRecord(evJoin, s2);

    // attention branch on the main stream
    prep_qkvr<<<(NLAYER * QKVR_C * EDIM + 255) / 256, 256>>>(Wq, Wk, Wv, Wr);
    const __nv_bfloat16* wbase = (const __nv_bfloat16*)pWqkvr;
    fused_layer<true><<<BATCH / F_SPB, 256, F_SMEM>>>(
        nullptr, 0L, sidx, emb, wbase, (__nv_bfloat16*)pAttA);
    fused_layer<false><<<BATCH / F_SPB, 256, F_SMEM>>>(
        (const __nv_bfloat16*)pAttA, (long)ATTFLAT, nullptr, nullptr,
        wbase + (size_t)QKVR_C * EDIM, (__nv_bfloat16*)pAttB);
    fused_layer<false><<<BATCH / F_SPB, 256, F_SMEM>>>(
        (const __nv_bfloat16*)pAttB, (long)ATTFLAT, nullptr, nullptr,
        wbase + (size_t)2 * QKVR_C * EDIM, (__nv_bfloat16*)pAttA);

    // join: head needs attA (main) + h2 (s2)
    cudaStreamWaitEvent(0, evJoin, 0);
    head_kernel<<<BATCH / 8, 256>>>(X, (const __nv_bfloat16*)pAttA, outW, linW, linb, out);
}

// round 17
// speedup vs baseline: 1.0456x; 1.0456x over previous
#include <cuda_runtime.h>
#include <cuda_bf16.h>
#include <cstdint>
#include <math.h>

// ---------------- problem constants ----------------
#define BATCH     32768
#define NSPARSE   26
#define NDENSE    13
#define VOCAB     10000
#define EDIM      64
#define NHEAD     2
#define DHEAD     32
#define NLAYER    3
#define H1DIM     256
#define H2DIM     128
#define DNNIN     1677
#define KPAD      1728            // 27*64 ; dnn cols: [emb 0..1663 | dense | pad]
#define XCOLS     39
#define ATTFLAT   (NSPARSE*EDIM)  // 1664
#define QKVR_C    256
#define MROWS     (BATCH*NSPARSE)
#define STACKW    (ATTFLAT + H2DIM)

// ---------------- scratch ----------------
__device__ __nv_bfloat16  g_attA[(size_t)BATCH * ATTFLAT];
__device__ __nv_bfloat16  g_attB[(size_t)BATCH * ATTFLAT];
__device__ __nv_bfloat16  g_dnn_bf[(size_t)BATCH * KPAD];
__device__ __nv_bfloat16  g_h1_bf[(size_t)BATCH * H1DIM];
__device__ float          g_h2[(size_t)BATCH * H2DIM];
__device__ float          g_attdot[(size_t)BATCH];
__device__ __nv_bfloat16  g_wqkvr_bf[NLAYER * QKVR_C * EDIM];  // [l][n][k]
__device__ __nv_bfloat16  g_w1_bf[H1DIM * KPAD];
__device__ __nv_bfloat16  g_w2_bf[H2DIM * H1DIM];

// ---------------- mma.sync helpers ----------------
__device__ __forceinline__ uint32_t smem_u32(const void* p) {
    uint32_t a;
    asm("{ .reg .u64 t; cvta.to.shared.u64 t, %1; cvt.u32.u64 %0, t; }" : "=r"(a) : "l"(p));
    return a;
}
#define LDSM_X4(d, addr) \
    asm volatile("ldmatrix.sync.aligned.m8n8.x4.shared.b16 {%0,%1,%2,%3}, [%4];" \
        : "=r"((d)[0]), "=r"((d)[1]), "=r"((d)[2]), "=r"((d)[3]) : "r"(addr))
#define LDSM_X4_T(d, addr) \
    asm volatile("ldmatrix.sync.aligned.m8n8.x4.trans.shared.b16 {%0,%1,%2,%3}, [%4];" \
        : "=r"((d)[0]), "=r"((d)[1]), "=r"((d)[2]), "=r"((d)[3]) : "r"(addr))

__device__ __forceinline__ void mma_bf16(float* c, const uint32_t* a,
                                         uint32_t b0, uint32_t b1) {
    asm volatile(
        "mma.sync.aligned.m16n8k16.row.col.f32.bf16.bf16.f32 "
        "{%0,%1,%2,%3},{%4,%5,%6,%7},{%8,%9},{%0,%1,%2,%3};"
        : "+f"(c[0]), "+f"(c[1]), "+f"(c[2]), "+f"(c[3])
        : "r"(a[0]), "r"(a[1]), "r"(a[2]), "r"(a[3]), "r"(b0), "r"(b1));
}
__device__ __forceinline__ uint32_t packbf(float a, float b) {
    __nv_bfloat162 h = __floats2bfloat162_rn(a, b);
    return *(uint32_t*)&h;
}

// ---------------- merged weight prep ----------------
#define PREP_W1_OFF  (NLAYER * QKVR_C * EDIM)
#define PREP_W2_OFF  (PREP_W1_OFF + H1DIM * KPAD)
#define PREP_TOTAL   (PREP_W2_OFF + H2DIM * H1DIM)
__global__ __launch_bounds__(256)
void prep_all(const float* __restrict__ Wq, const float* __restrict__ Wk,
              const float* __restrict__ Wv, const float* __restrict__ Wr,
              const float* __restrict__ W1, const float* __restrict__ W2) {
    int idx = blockIdx.x * 256 + threadIdx.x;
    if (idx < PREP_W1_OFF) {
        int l = idx >> 14, rem = idx & 16383;
        int n = rem >> 6, k = rem & 63;
        const float* Ws[4] = {Wq, Wk, Wv, Wr};
        g_wqkvr_bf[idx] = __float2bfloat16_rn(Ws[n >> 6][(l * EDIM + k) * EDIM + (n & 63)]);
    } else if (idx < PREP_W2_OFF) {
        int j = idx - PREP_W1_OFF;
        int n = j / KPAD, k = j % KPAD;
        float v = 0.f;
        if (k < ATTFLAT)               v = W1[(long)(13 + k) * H1DIM + n];
        else if (k < ATTFLAT + NDENSE) v = W1[(long)(k - ATTFLAT) * H1DIM + n];
        g_w1_bf[j] = __float2bfloat16_rn(v);
    } else {
        int j = idx - PREP_W2_OFF;
        int n = j / H1DIM, k = j % H1DIM;
        g_w2_bf[j] = __float2bfloat16_rn(W2[(long)k * H2DIM + n]);
    }
}

// ---------------- embedding gather: 4 threads/row, 4 independent float4 ----
__global__ __launch_bounds__(256)
void gather_emb(const int* __restrict__ sidx, const float* __restrict__ emb) {
    int t = threadIdx.x;
    int row = blockIdx.x * 64 + (t >> 2);
    int part = t & 3;
    int b = row / NSPARSE, f = row - b * NSPARSE;
    int vrow = sidx[(long)b * NSPARSE + f];
    const float* src = emb + ((long)f * VOCAB + vrow) * EDIM + part * 16;
    float4 a0 = *(const float4*)src;
    float4 a1 = *(const float4*)(src + 4);
    float4 a2 = *(const float4*)(src + 8);
    float4 a3 = *(const float4*)(src + 12);
    uint4 o0, o1;
    o0.x = packbf(a0.x, a0.y); o0.y = packbf(a0.z, a0.w);
    o0.z = packbf(a1.x, a1.y); o0.w = packbf(a1.z, a1.w);
    o1.x = packbf(a2.x, a2.y); o1.y = packbf(a2.z, a2.w);
    o1.z = packbf(a3.x, a3.y); o1.w = packbf(a3.z, a3.w);
    __nv_bfloat16* dst = g_dnn_bf + (long)b * KPAD + f * EDIM + part * 16;
    *(uint4*)dst       = o0;
    *(uint4*)(dst + 8) = o1;
}
__global__ __launch_bounds__(256)
void dense_pad(const float* __restrict__ X) {
    long idx = (long)blockIdx.x * 256 + threadIdx.x;
    int b = (int)(idx >> 6), cc = (int)(idx & 63);
    float v = (cc < NDENSE) ? X[(long)b * XCOLS + NSPARSE + cc] : 0.f;
    g_dnn_bf[(long)b * KPAD + ATTFLAT + cc] = __float2bfloat16_rn(v);
}

// ---------------- fused proj + attention layer (tensor-core attention) ----
// 256 threads, 4 samples/CTA. DOT=false: write att to Aout (layers 1,2).
// DOT=true (layer 3): epilogue dots relu(ov+res) with outW and writes
// g_attdot[sample] (deterministic smem combine; no att gmem round trip).
#define F_SPB   4
#define SQROWB  528
#define OFF_A   0
#define OFF_Q   (112 * 128)                    // 14336
#define F_SMEM  (OFF_Q + 112 * SQROWB)         // 73472

template<bool DOT>
__global__ __launch_bounds__(256, 3)
void fused_layer(const __nv_bfloat16* __restrict__ Ain, long sstride,
                 const __nv_bfloat16* __restrict__ W,
                 __nv_bfloat16* __restrict__ Aout,
                 const float* __restrict__ outW, float* __restrict__ attdot) {
    extern __shared__ __align__(1024) unsigned char sm[];
    const int tid = threadIdx.x, wid = tid >> 5, lane = tid & 31;
    const long b0 = (long)blockIdx.x * F_SPB;

    // A tile: 112 rows x 128 B (rows 104..111 zero), swizzled
#pragma unroll 4
    for (int u = tid; u < 896; u += 256) {
        int r = u >> 3, ck = u & 7;
        uint4 v = make_uint4(0u, 0u, 0u, 0u);
        if (r < 104) {
            int s = r / 26, f = r - s * 26;
            v = *(const uint4*)((const unsigned char*)(Ain + (b0 + s) * sstride + f * EDIM) + ck * 16);
        }
        *(uint4*)(sm + OFF_A + r * 128 + ((ck ^ (r & 7)) << 4)) = v;
    }

    // W fragments direct from gmem: wf[kk][nt][0..1] for this warp's 32 cols.
    uint32_t wf[4][4][2];
    {
        const __nv_bfloat16* Wl = W + (lane >> 2) * 64 + (lane & 3) * 2;
#pragma unroll
        for (int nt = 0; nt < 4; nt++) {
            const __nv_bfloat16* Wn = Wl + (wid * 32 + nt * 8) * 64;
#pragma unroll
            for (int kk = 0; kk < 4; kk++) {
                wf[kk][nt][0] = *(const uint32_t*)(Wn + kk * 16);
                wf[kk][nt][1] = *(const uint32_t*)(Wn + kk * 16 + 8);
            }
        }
    }
    __syncthreads();

    const uint32_t sA = smem_u32(sm + OFF_A);
    const int sel = lane >> 3, rr = lane & 7;
    const int g = lane >> 2, t4 = lane & 3;

    // 7 m-tiles of 16 rows
    for (int mt = 0; mt < 7; mt++) {
        float acc[4][4];
#pragma unroll
        for (int ni = 0; ni < 4; ni++)
#pragma unroll
            for (int q = 0; q < 4; q++) acc[ni][q] = 0.f;
#pragma unroll
        for (int kk = 0; kk < 4; kk++) {
            uint32_t a[4];
            int ra = mt * 16 + (sel & 1) * 8 + rr;
            LDSM_X4(a, sA + ra * 128 + ((uint32_t)((2 * kk + (sel >> 1)) ^ (ra & 7)) << 4));
#pragma unroll
            for (int nt = 0; nt < 4; nt++)
                mma_bf16(acc[nt], a, wf[kk][nt][0], wf[kk][nt][1]);
        }
#pragma unroll
        for (int ni = 0; ni < 4; ni++) {
            int col = wid * 32 + ni * 8 + 2 * t4;
            int r0 = mt * 16 + g;
            *(uint32_t*)(sm + OFF_Q + (long)r0 * SQROWB + col * 2) = packbf(acc[ni][0], acc[ni][1]);
            *(uint32_t*)(sm + OFF_Q + (long)(r0 + 8) * SQROWB + col * 2) = packbf(acc[ni][2], acc[ni][3]);
        }
    }
    __syncthreads();

    // ---------- attention on tensor cores: warp -> (s = w>>1, h = w&1) ----
    const int s = wid >> 1, h = wid & 1;
    const uint32_t sQ = smem_u32(sm + OFF_Q) + (uint32_t)(s * 26 * SQROWB);

    // scores S[32,32]
    float sc[2][4][4];
#pragma unroll
    for (int mt = 0; mt < 2; mt++)
#pragma unroll
        for (int nt = 0; nt < 4; nt++)
#pragma unroll
            for (int q = 0; q < 4; q++) sc[mt][nt][q] = 0.f;

#pragma unroll
    for (int ks = 0; ks < 2; ks++) {
        uint32_t qf[2][4];
#pragma unroll
        for (int mt = 0; mt < 2; mt++) {
            int r = mt * 16 + (sel & 1) * 8 + rr;
            LDSM_X4(qf[mt], sQ + (uint32_t)(r * SQROWB + h * 64 + ks * 32 + (sel >> 1) * 16));
        }
#pragma unroll
        for (int ntp = 0; ntp < 2; ntp++) {
            int jn = ntp * 16 + (sel >> 1) * 8 + rr;
            uint32_t kf[4];
            LDSM_X4(kf, sQ + (uint32_t)(jn * SQROWB + 128 + h * 64 + ks * 32 + (sel & 1) * 16));
#pragma unroll
            for (int mt = 0; mt < 2; mt++) {
                mma_bf16(sc[mt][ntp * 2],     qf[mt], kf[0], kf[1]);
                mma_bf16(sc[mt][ntp * 2 + 1], qf[mt], kf[2], kf[3]);
            }
        }
    }
    // mask cols >= 26
#pragma unroll
    for (int mt = 0; mt < 2; mt++)
#pragma unroll
        for (int q = 0; q < 4; q++) {
            int col = 24 + 2 * t4 + (q & 1);
            if (col >= 26) sc[mt][3][q] = -INFINITY;
        }
    // softmax per row; in-lane then quad shuffles
#pragma unroll
    for (int mt = 0; mt < 2; mt++) {
#pragma unroll
        for (int half = 0; half < 2; half++) {
            float m = -INFINITY;
#pragma unroll
            for (int nt = 0; nt < 4; nt++)
                m = fmaxf(m, fmaxf(sc[mt][nt][half * 2], sc[mt][nt][half * 2 + 1]));
            m = fmaxf(m, __shfl_xor_sync(0xffffffffu, m, 1));
            m = fmaxf(m, __shfl_xor_sync(0xffffffffu, m, 2));
            float ssum = 0.f;
#pragma unroll
            for (int nt = 0; nt < 4; nt++) {
                float e0 = __expf(sc[mt][nt][half * 2] - m);
                float e1 = __expf(sc[mt][nt][half * 2 + 1] - m);
                sc[mt][nt][half * 2] = e0; sc[mt][nt][half * 2 + 1] = e1;
                ssum += e0 + e1;
            }
            ssum += __shfl_xor_sync(0xffffffffu, ssum, 1);
            ssum += __shfl_xor_sync(0xffffffffu, ssum, 2);
            float inv = 1.f / ssum;
#pragma unroll
            for (int nt = 0; nt < 4; nt++) {
                sc[mt][nt][half * 2] *= inv;
                sc[mt][nt][half * 2 + 1] *= inv;
            }
        }
    }
    // P fragments -> PV
    float ov[2][4][4];
#pragma unroll
    for (int mt = 0; mt < 2; mt++)
#pragma unroll
        for (int nt = 0; nt < 4; nt++)
#pragma unroll
            for (int q = 0; q < 4; q++) ov[mt][nt][q] = 0.f;

#pragma unroll
    for (int ks = 0; ks < 2; ks++) {
        uint32_t vb[2][4];
#pragma unroll
        for (int ntp = 0; ntp < 2; ntp++) {
            int j = ks * 16 + (sel & 1) * 8 + rr;
            int ntile = ntp * 2 + (sel >> 1);
            LDSM_X4_T(vb[ntp], sQ + (uint32_t)(j * SQROWB + 256 + h * 64 + ntile * 16));
        }
#pragma unroll
        for (int mt = 0; mt < 2; mt++) {
            uint32_t pa[4];
            pa[0] = packbf(sc[mt][2 * ks][0], sc[mt][2 * ks][1]);
            pa[1] = packbf(sc[mt][2 * ks][2], sc[mt][2 * ks][3]);
            pa[2] = packbf(sc[mt][2 * ks + 1][0], sc[mt][2 * ks + 1][1]);
            pa[3] = packbf(sc[mt][2 * ks + 1][2], sc[mt][2 * ks + 1][3]);
#pragma unroll
            for (int ntp = 0; ntp < 2; ntp++) {
                mma_bf16(ov[mt][ntp * 2],     pa, vb[ntp][0], vb[ntp][1]);
                mma_bf16(ov[mt][ntp * 2 + 1], pa, vb[ntp][2], vb[ntp][3]);
            }
        }
    }
    // residual (cols 192+h*32 -> bytes 384+h*64) + relu; then store or dot
    if (!DOT) {
        __nv_bfloat16* outb = Aout + (b0 + s) * ATTFLAT + h * DHEAD;
#pragma unroll
        for (int mt = 0; mt < 2; mt++) {
#pragma unroll
            for (int nt = 0; nt < 4; nt++) {
                int col = nt * 8 + 2 * t4;
                int r0 = mt * 16 + g;
                {
                    uint32_t ru = *(const uint32_t*)(sm + OFF_Q + (s * 26 + r0) * SQROWB + 384 + h * 64 + col * 2);
                    float2 rf = __bfloat1622float2(*(__nv_bfloat162*)&ru);
                    float o0 = fmaxf(ov[mt][nt][0] + rf.x, 0.f);
                    float o1 = fmaxf(ov[mt][nt][1] + rf.y, 0.f);
                    *(uint32_t*)(outb + (size_t)r0 * EDIM + col) = packbf(o0, o1);
                }
                int r1 = r0 + 8;
                if (mt == 0 || g < 2) {
                    uint32_t ru = *(const uint32_t*)(sm + OFF_Q + (s * 26 + r1) * SQROWB + 384 + h * 64 + col * 2);
                    float2 rf = __bfloat1622float2(*(__nv_bfloat162*)&ru);
                    float o0 = fmaxf(ov[mt][nt][2] + rf.x, 0.f);
                    float o1 = fmaxf(ov[mt][nt][3] + rf.y, 0.f);
                    *(uint32_t*)(outb + (size_t)r1 * EDIM + col) = packbf(o0, o1);
                }
            }
        }
    } else {
        float partial = 0.f;
#pragma unroll
        for (int mt = 0; mt < 2; mt++) {
#pragma unroll
            for (int nt = 0; nt < 4; nt++) {
                int col = nt * 8 + 2 * t4;
                int r0 = mt * 16 + g;
                {
                    uint32_t ru = *(const uint32_t*)(sm + OFF_Q + (s * 26 + r0) * SQROWB + 384 + h * 64 + col * 2);
                    float2 rf = __bfloat1622float2(*(__nv_bfloat162*)&ru);
                    float o0 = fmaxf(ov[mt][nt][0] + rf.x, 0.f);
                    float o1 = fmaxf(ov[mt][nt][1] + rf.y, 0.f);
                    // bf16-round to match reference att precision path
                    o0 = __bfloat162float(__float2bfloat16_rn(o0));
                    o1 = __bfloat162float(__float2bfloat16_rn(o1));
                    float2 w = *(const float2*)(outW + r0 * EDIM + h * DHEAD + col);
                    partial += o0 * w.x + o1 * w.y;
                }
                int r1 = r0 + 8;
                if (mt == 0 || g < 2) {
                    uint32_t ru = *(const uint32_t*)(sm + OFF_Q + (s * 26 + r1) * SQROWB + 384 + h * 64 + col * 2);
                    float2 rf = __bfloat1622float2(*(__nv_bfloat162*)&ru);
                    float o0 = fmaxf(ov[mt][nt][2] + rf.x, 0.f);
                    float o1 = fmaxf(ov[mt][nt][3] + rf.y, 0.f);
                    o0 = __bfloat162float(__float2bfloat16_rn(o0));
                    o1 = __bfloat162float(__float2bfloat16_rn(o1));
                    float2 w = *(const float2*)(outW + r1 * EDIM + h * DHEAD + col);
                    partial += o0 * w.x + o1 * w.y;
                }
            }
        }
#pragma unroll
        for (int o = 16; o > 0; o >>= 1)
            partial += __shfl_xor_sync(0xffffffffu, partial, o);
        float* red = (float*)(sm + OFF_A);   // A region dead in attn phase
        if (lane == 0) red[wid] = partial;
        __syncthreads();
        if (tid < F_SPB)
            attdot[b0 + tid] = red[2 * tid] + red[2 * tid + 1];
    }
}

// ---------------- bf16 mma.sync GEMM (dnn layers) ----------------
template<int KTOT, int NTFULL, bool RELU, bool BF16OUT>
__global__ __launch_bounds__(256)
void gemm_mma(const __nv_bfloat16* __restrict__ A,
              const __nv_bfloat16* __restrict__ Bop,
              const float* __restrict__ bias,
              void* __restrict__ Cout) {
    __shared__ __align__(1024) unsigned char smA[128 * 128];
    __shared__ __align__(1024) unsigned char smB[128 * 128];
    const int tid = threadIdx.x;
    const int wid = tid >> 5, lane = tid & 31;
    const int wm = wid & 3, wn = wid >> 2;
    const long m0 = (long)blockIdx.x * 128;
    const int n0 = blockIdx.y * 128;

    float acc[2][8][4];
#pragma unroll
    for (int mi = 0; mi < 2; mi++)
#pragma unroll
        for (int ni = 0; ni < 8; ni++)
#pragma unroll
            for (int q = 0; q < 4; q++) acc[mi][ni][q] = 0.f;

    const uint32_t sA = smem_u32(smA), sB = smem_u32(smB);
    const int sel = lane >> 3, rr = lane & 7;
    const int arow0 = wm * 32 + (sel & 1) * 8 + rr;
    const int ahi = sel >> 1;
    const int brow0 = wn * 64 + (sel >> 1) * 8 + rr;
    const int bhi = sel & 1;

    const int NCH = KTOT / 64;
    for (int ch = 0; ch < NCH; ch++) {
        const unsigned char* Ag = (const unsigned char*)A + (m0 * KTOT + (long)ch * 64) * 2;
        const unsigned char* Bg = (const unsigned char*)Bop + (((long)n0 * KTOT) + (long)ch * 64) * 2;
#pragma unroll 2
        for (int u = tid; u < 1024; u += 256) {
            int r = u >> 3, ck = u & 7;
            uint32_t so = (uint32_t)(r * 128 + ((ck ^ (r & 7)) << 4));
            *(uint4*)(smA + so) = *(const uint4*)(Ag + (long)r * (KTOT * 2) + ck * 16);
            *(uint4*)(smB + so) = *(const uint4*)(Bg + (long)r * (KTOT * 2) + ck * 16);
        }
        __syncthreads();
#pragma unroll
        for (int kk = 0; kk < 4; kk++) {
            uint32_t a[2][4];
#pragma unroll
            for (int mi = 0; mi < 2; mi++) {
                int r = arow0 + mi * 16;
                LDSM_X4(a[mi], sA + r * 128 + ((uint32_t)((2 * kk + ahi) ^ (r & 7)) << 4));
            }
#pragma unroll
            for (int nip = 0; nip < 4; nip++) {
                int r = brow0 + nip * 16;
                uint32_t b[4];
                LDSM_X4(b, sB + r * 128 + ((uint32_t)((2 * kk + bhi) ^ (r & 7)) << 4));
#pragma unroll
                for (int mi = 0; mi < 2; mi++) {
                    mma_bf16(acc[mi][nip * 2],     a[mi], b[0], b[1]);
                    mma_bf16(acc[mi][nip * 2 + 1], a[mi], b[2], b[3]);
                }
            }
        }
        __syncthreads();
    }

    const int g = lane >> 2, t = lane & 3;
#pragma unroll
    for (int mi = 0; mi < 2; mi++) {
#pragma unroll
        for (int ni = 0; ni < 8; ni++) {
            int col = n0 + wn * 64 + ni * 8 + 2 * t;
            long r0 = m0 + wm * 32 + mi * 16 + g;
            float c0 = acc[mi][ni][0], c1 = acc[mi][ni][1];
            float c2 = acc[mi][ni][2], c3 = acc[mi][ni][3];
            if (bias != nullptr) {
                float bb0 = bias[col], bb1 = bias[col + 1];
                c0 += bb0; c1 += bb1; c2 += bb0; c3 += bb1;
            }
            if (RELU) {
                c0 = fmaxf(c0, 0.f); c1 = fmaxf(c1, 0.f);
                c2 = fmaxf(c2, 0.f); c3 = fmaxf(c3, 0.f);
            }
            if (BF16OUT) {
                __nv_bfloat16* base = (__nv_bfloat16*)Cout;
                *(uint32_t*)(base + r0 * NTFULL + col)       = packbf(c0, c1);
                *(uint32_t*)(base + (r0 + 8) * NTFULL + col) = packbf(c2, c3);
            } else {
                float* base = (float*)Cout;
                *(float2*)(base + r0 * NTFULL + col)       = make_float2(c0, c1);
                *(float2*)(base + (r0 + 8) * NTFULL + col) = make_float2(c2, c3);
            }
        }
    }
}

// ---------------- head: h2 dot + linear + attdot + sigmoid ----------------
__global__ __launch_bounds__(256)
void head_kernel(const float* __restrict__ X,
                 const float* __restrict__ attdot,
                 const float* __restrict__ outW,
                 const float* __restrict__ linW, const float* __restrict__ linb,
                 float* __restrict__ out) {
    __shared__ __align__(16) float soW[H2DIM];
    int tid = threadIdx.x;
    if (tid < H2DIM) soW[tid] = outW[ATTFLAT + tid];
    __syncthreads();
    int warp = tid >> 5, lane = tid & 31;
    int s = blockIdx.x * 8 + warp;
    float acc;
    {
        const float4* hp = (const float4*)&g_h2[(size_t)s * H2DIM];
        float4 a = hp[lane];
        float4 w = ((const float4*)soW)[lane];
        acc = a.x * w.x + a.y * w.y + a.z * w.z + a.w * w.w;
    }
    float al = X[(size_t)s * XCOLS + lane] * linW[lane];
    if (lane < XCOLS - 32) al += X[(size_t)s * XCOLS + 32 + lane] * linW[32 + lane];
#pragma unroll
    for (int o = 16; o > 0; o >>= 1) {
        acc += __shfl_xor_sync(0xffffffffu, acc, o);
        al  += __shfl_xor_sync(0xffffffffu, al, o);
    }
    if (lane == 0) {
        float lin = fmaxf(al + linb[0], 0.f);
        out[s] = 1.f / (1.f + expf(-(lin + acc + attdot[s])));
    }
}

// ---------------- launcher ----------------
extern "C" void kernel_launch(void* const* d_in, const int* in_sizes, int n_in,
                              void* d_out, int out_size) {
    (void)in_sizes; (void)n_in; (void)out_size;
    const float* X    = (const float*)d_in[0];
    const int*   sidx = (const int*)  d_in[1];
    const float* emb  = (const float*)d_in[2];
    const float* Wq   = (const float*)d_in[3];
    const float* Wk   = (const float*)d_in[4];
    const float* Wv   = (const float*)d_in[5];
    const float* Wr   = (const float*)d_in[6];
    const float* W1   = (const float*)d_in[7];
    const float* b1   = (const float*)d_in[8];
    const float* W2   = (const float*)d_in[9];
    const float* b2   = (const float*)d_in[10];
    const float* outW = (const float*)d_in[11];
    const float* linW = (const float*)d_in[12];
    const float* linb = (const float*)d_in[13];
    float* out = (float*)d_out;

    void *pAttA, *pAttB, *pDnn, *pH1, *pH2, *pDot, *pWqkvr, *pW1b, *pW2b;
    cudaGetSymbolAddress(&pAttA,  g_attA);
    cudaGetSymbolAddress(&pAttB,  g_attB);
    cudaGetSymbolAddress(&pDnn,   g_dnn_bf);
    cudaGetSymbolAddress(&pH1,    g_h1_bf);
    cudaGetSymbolAddress(&pH2,    g_h2);
    cudaGetSymbolAddress(&pDot,   g_attdot);
    cudaGetSymbolAddress(&pWqkvr, g_wqkvr_bf);
    cudaGetSymbolAddress(&pW1b,   g_w1_bf);
    cudaGetSymbolAddress(&pW2b,   g_w2_bf);

    cudaFuncSetAttribute((const void*)fused_layer<false>,
                         cudaFuncAttributeMaxDynamicSharedMemorySize, F_SMEM);
    cudaFuncSetAttribute((const void*)fused_layer<true>,
                         cudaFuncAttributeMaxDynamicSharedMemorySize, F_SMEM);

    static cudaStream_t s2 = nullptr;
    static cudaEvent_t evFork = nullptr, evJoin = nullptr;
    if (s2 == nullptr) {
        cudaStreamCreateWithFlags(&s2, cudaStreamNonBlocking);
        cudaEventCreateWithFlags(&evFork, cudaEventDisableTiming);
        cudaEventCreateWithFlags(&evJoin, cudaEventDisableTiming);
    }

    // common producers on the main (capture) stream
    prep_all<<<PREP_TOTAL / 256, 256>>>(Wq, Wk, Wv, Wr, W1, W2);
    gather_emb<<<MROWS / 64, 256>>>(sidx, emb);
    dense_pad<<<BATCH * 64 / 256, 256>>>(X);

    // fork: DNN branch on s2
    cudaEventRecord(evFork, 0);
    cudaStreamWaitEvent(s2, evFork, 0);
    gemm_mma<KPAD, H1DIM, true, true><<<dim3(BATCH / 128, H1DIM / 128), 256, 0, s2>>>(
        (const __nv_bfloat16*)pDnn, (const __nv_bfloat16*)pW1b, b1, pH1);
    gemm_mma<H1DIM, H2DIM, true, false><<<dim3(BATCH / 128, 1), 256, 0, s2>>>(
        (const __nv_bfloat16*)pH1, (const __nv_bfloat16*)pW2b, b2, pH2);
    cudaEventRecord(evJoin, s2);

    // attention branch on the main stream (layer 3 emits attdot directly)
    const __nv_bfloat16* wbase = (const __nv_bfloat16*)pWqkvr;
    fused_layer<false><<<BATCH / F_SPB, 256, F_SMEM>>>(
        (const __nv_bfloat16*)pDnn, (long)KPAD, wbase,
        (__nv_bfloat16*)pAttA, nullptr, nullptr);
    fused_layer<false><<<BATCH / F_SPB, 256, F_SMEM>>>(
        (const __nv_bfloat16*)pAttA, (long)ATTFLAT, wbase + (size_t)QKVR_C * EDIM,
        (__nv_bfloat16*)pAttB, nullptr, nullptr);
    fused_layer<true><<<BATCH / F_SPB, 256, F_SMEM>>>(
        (const __nv_bfloat16*)pAttB, (long)ATTFLAT, wbase + (size_t)2 * QKVR_C * EDIM,
        nullptr, outW, (float*)pDot);

    // join: head needs attdot (main) + h2 (s2)
    cudaStreamWaitEvent(0, evJoin, 0);
    head_kernel<<<BATCH / 8, 256>>>(X, (const float*)pDot, outW, linW, linb, out);
}